// round 6
// baseline (speedup 1.0000x reference)
#include <cuda_runtime.h>
#include <cuda_bf16.h>
#include <cstdint>

// Problem constants (shapes fixed by the dataset).
#define MAXN_NODES 50000
#define SMS 136                       // padded smem row stride in bf16 elems (128 + 8)
#define NPLANE ((size_t)MAXN_NODES * 128)

// Scratch (static device allocations are allowed; cudaMalloc is not).
// Planes 0-3: K_t, 4-7: Q_t, 8-11: V_t * 0.25. Plane 12 (self-loop) goes straight to d_out.
__device__ float          g_feat[(size_t)12 * MAXN_NODES * 128];   // ~307 MB
__device__ __nv_bfloat16  g_Wh[13 * 128 * 128];
__device__ __nv_bfloat16  g_Wl[13 * 128 * 128];
__device__ float          g_bias[13 * 128];

// ---------------------------------------------------------------------------
// Pack weights into 13 [k=128][n=128] bf16 hi/lo planes + bias vector.
// Planes: 0-3 Wk, 4-7 Wq, 8-11 0.25*Wv, 12 = 0.25*sum_t Ws[t].
// ---------------------------------------------------------------------------
__global__ void pack_weights_kernel(const float* __restrict__ Wk, const float* __restrict__ bk,
                                    const float* __restrict__ Wq, const float* __restrict__ bq,
                                    const float* __restrict__ Wv, const float* __restrict__ bv,
                                    const float* __restrict__ Ws, const float* __restrict__ bs)
{
    int idx = blockIdx.x * blockDim.x + threadIdx.x;
    if (idx < 13 * 16384) {
        int p   = idx >> 14;
        int off = idx & 16383;
        float v;
        if (p < 4)       v = Wk[p * 16384 + off];
        else if (p < 8)  v = Wq[(p - 4) * 16384 + off];
        else if (p < 12) v = 0.25f * Wv[(p - 8) * 16384 + off];
        else             v = 0.25f * (Ws[off] + Ws[16384 + off] + Ws[32768 + off] + Ws[49152 + off]);
        __nv_bfloat16 h = __float2bfloat16(v);
        g_Wh[idx] = h;
        g_Wl[idx] = __float2bfloat16(v - __bfloat162float(h));
    }
    if (idx < 13 * 128) {
        int p   = idx >> 7;
        int off = idx & 127;
        float v;
        if (p < 4)       v = bk[p * 128 + off];
        else if (p < 8)  v = bq[(p - 4) * 128 + off];
        else if (p < 12) v = 0.25f * bv[(p - 8) * 128 + off];
        else             v = 0.25f * (bs[off] + bs[128 + off] + bs[256 + off] + bs[384 + off]);
        g_bias[idx] = v;
    }
}

// ---------------------------------------------------------------------------
// Tensor-core GEMM: C[N,13*128] = x[N,128] @ Wcat[128,13*128] + bias
// bf16 split (hi+lo on both operands, 3 accumulating HMMAs) for fp32-like accuracy.
// Grid: (13 planes, ceil(N/128) row tiles). 256 threads = 8 warps (2m x 4n),
// warp tile 64x32, K=128 done in 8 k-steps of 16.
// ---------------------------------------------------------------------------
__device__ __forceinline__ void mma16816(float* c, const unsigned* a, const unsigned* b)
{
    asm volatile(
        "mma.sync.aligned.m16n8k16.row.col.f32.bf16.bf16.f32 "
        "{%0,%1,%2,%3}, {%4,%5,%6,%7}, {%8,%9}, {%0,%1,%2,%3};\n"
        : "+f"(c[0]), "+f"(c[1]), "+f"(c[2]), "+f"(c[3])
        : "r"(a[0]), "r"(a[1]), "r"(a[2]), "r"(a[3]), "r"(b[0]), "r"(b[1]));
}

__device__ __forceinline__ void ldsm4(unsigned* r, uint32_t addr)
{
    asm volatile("ldmatrix.sync.aligned.m8n8.x4.shared.b16 {%0,%1,%2,%3}, [%4];\n"
                 : "=r"(r[0]), "=r"(r[1]), "=r"(r[2]), "=r"(r[3]) : "r"(addr));
}
__device__ __forceinline__ void ldsm4t(unsigned* r, uint32_t addr)
{
    asm volatile("ldmatrix.sync.aligned.m8n8.x4.trans.shared.b16 {%0,%1,%2,%3}, [%4];\n"
                 : "=r"(r[0]), "=r"(r[1]), "=r"(r[2]), "=r"(r[3]) : "r"(addr));
}

__global__ void __launch_bounds__(256, 1)
gemm_kernel(const float* __restrict__ X, float* __restrict__ out, int N)
{
    extern __shared__ __nv_bfloat16 sm[];
    __nv_bfloat16* Ahs = sm;
    __nv_bfloat16* Als = sm + 128 * SMS;
    __nv_bfloat16* Bhs = sm + 2 * 128 * SMS;
    __nv_bfloat16* Bls = sm + 3 * 128 * SMS;

    int plane   = blockIdx.x;
    int rowBase = blockIdx.y * 128;
    int tid     = threadIdx.x;

    // Load W plane (bf16 hi/lo) into padded smem.
    {
        const uint4* srcH = (const uint4*)(g_Wh + plane * 16384);
        const uint4* srcL = (const uint4*)(g_Wl + plane * 16384);
#pragma unroll
        for (int i = 0; i < 8; i++) {
            int chunk = tid + i * 256;
            int row = chunk >> 4;
            int c8  = (chunk & 15) * 8;
            *(uint4*)(Bhs + row * SMS + c8) = srcH[chunk];
            *(uint4*)(Bls + row * SMS + c8) = srcL[chunk];
        }
    }
    // Load x tile (fp32) and split into bf16 hi/lo.
    {
#pragma unroll
        for (int i = 0; i < 16; i++) {
            int chunk = tid + i * 256;
            int row = chunk >> 5;
            int c4  = (chunk & 31) * 4;
            int grow = rowBase + row;
            float4 v = make_float4(0.f, 0.f, 0.f, 0.f);
            if (grow < N) v = *(const float4*)(X + (size_t)grow * 128 + c4);
            float f[4] = {v.x, v.y, v.z, v.w};
#pragma unroll
            for (int j = 0; j < 4; j++) {
                __nv_bfloat16 h = __float2bfloat16(f[j]);
                Ahs[row * SMS + c4 + j] = h;
                Als[row * SMS + c4 + j] = __float2bfloat16(f[j] - __bfloat162float(h));
            }
        }
    }
    __syncthreads();

    int w    = tid >> 5;
    int lane = tid & 31;
    int wm   = (w & 1) * 64;   // warp row offset
    int wn   = (w >> 1) * 32;  // warp col offset
    int lrow = lane & 15;
    int lcol = (lane >> 4) * 8;

    float acc[4][4][4];
#pragma unroll
    for (int i = 0; i < 4; i++)
#pragma unroll
        for (int j = 0; j < 4; j++)
#pragma unroll
            for (int k2 = 0; k2 < 4; k2++) acc[i][j][k2] = 0.f;

#pragma unroll
    for (int ks = 0; ks < 8; ks++) {
        int kb = ks * 16;
        unsigned ah[4][4], al[4][4], bh[2][4], bl[2][4];
#pragma unroll
        for (int mt = 0; mt < 4; mt++) {
            const __nv_bfloat16* pa = Ahs + (wm + mt * 16 + lrow) * SMS + kb + lcol;
            ldsm4(ah[mt], (uint32_t)__cvta_generic_to_shared(pa));
            const __nv_bfloat16* pl = Als + (wm + mt * 16 + lrow) * SMS + kb + lcol;
            ldsm4(al[mt], (uint32_t)__cvta_generic_to_shared(pl));
        }
#pragma unroll
        for (int np = 0; np < 2; np++) {
            const __nv_bfloat16* pb = Bhs + (kb + lrow) * SMS + wn + np * 16 + lcol;
            ldsm4t(bh[np], (uint32_t)__cvta_generic_to_shared(pb));
            const __nv_bfloat16* pb2 = Bls + (kb + lrow) * SMS + wn + np * 16 + lcol;
            ldsm4t(bl[np], (uint32_t)__cvta_generic_to_shared(pb2));
        }
#pragma unroll
        for (int mt = 0; mt < 4; mt++)
#pragma unroll
            for (int nt = 0; nt < 4; nt++) {
                const unsigned* bhp = &bh[nt >> 1][(nt & 1) * 2];
                const unsigned* blp = &bl[nt >> 1][(nt & 1) * 2];
                mma16816(acc[mt][nt], ah[mt], bhp);   // Ah*Bh
                mma16816(acc[mt][nt], ah[mt], blp);   // Ah*Bl
                mma16816(acc[mt][nt], al[mt], bhp);   // Al*Bh
            }
    }

    // Epilogue: bias add + store. Plane 12 writes d_out (self-loop base term).
    float* dst = (plane == 12) ? out : (g_feat + (size_t)plane * NPLANE);
    const float* bias = g_bias + plane * 128;
    int g  = lane >> 2;
    int tg = lane & 3;
#pragma unroll
    for (int nt = 0; nt < 4; nt++) {
        int col = wn + nt * 8 + tg * 2;
        float b0 = bias[col], b1 = bias[col + 1];
#pragma unroll
        for (int mt = 0; mt < 4; mt++) {
            int r = rowBase + wm + mt * 16 + g;
            if (r < N) {
                float2 v0 = make_float2(acc[mt][nt][0] + b0, acc[mt][nt][1] + b1);
                *(float2*)(dst + (size_t)r * 128 + col) = v0;
            }
            if (r + 8 < N) {
                float2 v1 = make_float2(acc[mt][nt][2] + b0, acc[mt][nt][3] + b1);
                *(float2*)(dst + (size_t)(r + 8) * 128 + col) = v1;
            }
        }
    }
}

// ---------------------------------------------------------------------------
// Edge scatter for one edge type t: out[dst] += sigmoid(K_t[dst]+Q_t[src]) * V'_t[src]
// (V' already carries the 1/T mean factor). Ballot-compaction: 32 edges per
// warp window, all 32 lanes cooperate on each matching edge (4 feats/lane).
// red.global.add.v4.f32 quarters the atomic op count.
// ---------------------------------------------------------------------------
__global__ void __launch_bounds__(256)
edge_kernel(const int* __restrict__ ei, const int* __restrict__ et,
            float* __restrict__ out, int E, int t)
{
    const float4* K4 = (const float4*)(g_feat + (size_t)t * NPLANE);
    const float4* Q4 = (const float4*)(g_feat + (size_t)(4 + t) * NPLANE);
    const float4* V4 = (const float4*)(g_feat + (size_t)(8 + t) * NPLANE);

    int lane   = threadIdx.x & 31;
    int warp   = blockIdx.x * (blockDim.x >> 5) + (threadIdx.x >> 5);
    int nwarps = gridDim.x * (blockDim.x >> 5);

    for (int base = warp * 32; base < E; base += nwarps * 32) {
        int e  = base + lane;
        int ty = -1, s0 = 0, d0 = 0;
        if (e < E) { ty = et[e]; s0 = ei[e]; d0 = ei[E + e]; }
        unsigned m = __ballot_sync(0xffffffffu, ty == t);
        while (m) {
            int b = __ffs(m) - 1;
            m &= (m - 1);
            int src = __shfl_sync(0xffffffffu, s0, b);
            int dst = __shfl_sync(0xffffffffu, d0, b);
            float4 kk = K4[(size_t)dst * 32 + lane];
            float4 qq = Q4[(size_t)src * 32 + lane];
            float4 vv = V4[(size_t)src * 32 + lane];
            float4 r;
            r.x = vv.x * __fdividef(1.f, 1.f + __expf(-(kk.x + qq.x)));
            r.y = vv.y * __fdividef(1.f, 1.f + __expf(-(kk.y + qq.y)));
            r.z = vv.z * __fdividef(1.f, 1.f + __expf(-(kk.z + qq.z)));
            r.w = vv.w * __fdividef(1.f, 1.f + __expf(-(kk.w + qq.w)));
            float* p = out + (size_t)dst * 128 + lane * 4;
            asm volatile("red.global.add.v4.f32 [%0], {%1,%2,%3,%4};\n"
                         :: "l"(p), "f"(r.x), "f"(r.y), "f"(r.z), "f"(r.w)
                         : "memory");
        }
    }
}

// ---------------------------------------------------------------------------
// Launch: pack -> GEMM (plane 12 initializes d_out) -> 4 per-type edge passes.
// All plain kernel launches on the capture stream; no allocs, no syncs.
// ---------------------------------------------------------------------------
extern "C" void kernel_launch(void* const* d_in, const int* in_sizes, int n_in,
                              void* d_out, int out_size)
{
    const float* x  = (const float*)d_in[0];
    const int*   ei = (const int*)d_in[1];
    const int*   et = (const int*)d_in[2];
    const float* Wk = (const float*)d_in[3];
    const float* bk = (const float*)d_in[4];
    const float* Wq = (const float*)d_in[5];
    const float* bq = (const float*)d_in[6];
    const float* Wv = (const float*)d_in[7];
    const float* bv = (const float*)d_in[8];
    const float* Ws = (const float*)d_in[9];
    const float* bb = (const float*)d_in[10];
    float* out = (float*)d_out;

    int N = in_sizes[0] / 128;
    int E = in_sizes[2];

    const int smem_bytes = 4 * 128 * SMS * (int)sizeof(__nv_bfloat16);  // 139264
    cudaFuncSetAttribute(gemm_kernel, cudaFuncAttributeMaxDynamicSharedMemorySize, smem_bytes);

    pack_weights_kernel<<<(13 * 16384 + 255) / 256, 256>>>(Wk, bk, Wq, bq, Wv, bv, Ws, bb);

    dim3 gg(13, (N + 127) / 128);
    gemm_kernel<<<gg, 256, smem_bytes>>>(x, out, N);

    for (int t = 0; t < 4; t++) {
        edge_kernel<<<1024, 256>>>(ei, et, out, E, t);
    }
}

// round 8
// speedup vs baseline: 1.8346x; 1.8346x over previous
#include <cuda_runtime.h>
#include <cuda_bf16.h>
#include <cuda_fp16.h>
#include <cstdint>

// Problem constants (shapes fixed by the dataset).
#define MAXN_NODES 50000
#define SMS 136                       // padded smem row stride in fp16 elems (128 + 8)
#define NPLANE_H ((size_t)MAXN_NODES * 128)

// Scratch (static device arrays; cudaMalloc is forbidden).
// g_K[t][node][128]  : K_t features, fp16
// g_QV[t][node][256] : Q_t (cols 0-127) and 0.25*V_t (cols 128-255) interleaved per node, fp16
__device__ __half g_K [(size_t)4 * MAXN_NODES * 128];
__device__ __half g_QV[(size_t)4 * MAXN_NODES * 256];
__device__ __half g_W [13 * 128 * 128];     // fp16 weight planes, [k][n]
__device__ float  g_bias[13 * 128];

// ---------------------------------------------------------------------------
// Pack weights into 13 [k=128][n=128] fp16 planes + fp32 bias vector.
// Planes: 0-3 Wk, 4-7 Wq, 8-11 0.25*Wv, 12 = 0.25*sum_t Ws[t].
// ---------------------------------------------------------------------------
__global__ void pack_weights_kernel(const float* __restrict__ Wk, const float* __restrict__ bk,
                                    const float* __restrict__ Wq, const float* __restrict__ bq,
                                    const float* __restrict__ Wv, const float* __restrict__ bv,
                                    const float* __restrict__ Ws, const float* __restrict__ bs)
{
    int idx = blockIdx.x * blockDim.x + threadIdx.x;
    if (idx < 13 * 16384) {
        int p   = idx >> 14;
        int off = idx & 16383;
        float v;
        if (p < 4)       v = Wk[p * 16384 + off];
        else if (p < 8)  v = Wq[(p - 4) * 16384 + off];
        else if (p < 12) v = 0.25f * Wv[(p - 8) * 16384 + off];
        else             v = 0.25f * (Ws[off] + Ws[16384 + off] + Ws[32768 + off] + Ws[49152 + off]);
        g_W[idx] = __float2half_rn(v);
    }
    if (idx < 13 * 128) {
        int p   = idx >> 7;
        int off = idx & 127;
        float v;
        if (p < 4)       v = bk[p * 128 + off];
        else if (p < 8)  v = bq[(p - 4) * 128 + off];
        else if (p < 12) v = 0.25f * bv[(p - 8) * 128 + off];
        else             v = 0.25f * (bs[off] + bs[128 + off] + bs[256 + off] + bs[384 + off]);
        g_bias[idx] = v;
    }
}

// ---------------------------------------------------------------------------
// Tensor-core GEMM: C[N,13*128] = x[N,128] @ Wcat[128,13*128] + bias
// Single-pass fp16 HMMA (f32 accumulate). Grid: (13 planes, ceil(N/128)).
// 256 threads = 8 warps (2m x 4n), warp tile 64x32, K in 8 steps of 16.
// ---------------------------------------------------------------------------
__device__ __forceinline__ void mma16816(float* c, const unsigned* a, const unsigned* b)
{
    asm volatile(
        "mma.sync.aligned.m16n8k16.row.col.f32.f16.f16.f32 "
        "{%0,%1,%2,%3}, {%4,%5,%6,%7}, {%8,%9}, {%0,%1,%2,%3};\n"
        : "+f"(c[0]), "+f"(c[1]), "+f"(c[2]), "+f"(c[3])
        : "r"(a[0]), "r"(a[1]), "r"(a[2]), "r"(a[3]), "r"(b[0]), "r"(b[1]));
}

__device__ __forceinline__ void ldsm4(unsigned* r, uint32_t addr)
{
    asm volatile("ldmatrix.sync.aligned.m8n8.x4.shared.b16 {%0,%1,%2,%3}, [%4];\n"
                 : "=r"(r[0]), "=r"(r[1]), "=r"(r[2]), "=r"(r[3]) : "r"(addr));
}
__device__ __forceinline__ void ldsm4t(unsigned* r, uint32_t addr)
{
    asm volatile("ldmatrix.sync.aligned.m8n8.x4.trans.shared.b16 {%0,%1,%2,%3}, [%4];\n"
                 : "=r"(r[0]), "=r"(r[1]), "=r"(r[2]), "=r"(r[3]) : "r"(addr));
}

__global__ void __launch_bounds__(256, 2)
gemm_kernel(const float* __restrict__ X, float* __restrict__ out, int N)
{
    extern __shared__ __half sm[];
    __half* As = sm;                // [128][SMS]
    __half* Bs = sm + 128 * SMS;    // [128][SMS], [k][n]

    int plane   = blockIdx.x;
    int rowBase = blockIdx.y * 128;
    int tid     = threadIdx.x;

    // Load W plane (fp16) into padded smem: 16384 halves = 2048 uint4 chunks.
    {
        const uint4* srcW = (const uint4*)(g_W + plane * 16384);
#pragma unroll
        for (int i = 0; i < 8; i++) {
            int chunk = tid + i * 256;
            int row = chunk >> 4;
            int c8  = (chunk & 15) * 8;
            *(uint4*)(Bs + row * SMS + c8) = srcW[chunk];
        }
    }
    // Load x tile (fp32), convert to fp16.
    {
#pragma unroll
        for (int i = 0; i < 16; i++) {
            int chunk = tid + i * 256;
            int row = chunk >> 5;
            int c4  = (chunk & 31) * 4;
            int grow = rowBase + row;
            float4 v = make_float4(0.f, 0.f, 0.f, 0.f);
            if (grow < N) v = *(const float4*)(X + (size_t)grow * 128 + c4);
            __half2 h01 = __floats2half2_rn(v.x, v.y);
            __half2 h23 = __floats2half2_rn(v.z, v.w);
            uint2 packed = make_uint2(*(unsigned*)&h01, *(unsigned*)&h23);
            *(uint2*)(As + row * SMS + c4) = packed;
        }
    }
    __syncthreads();

    int w    = tid >> 5;
    int lane = tid & 31;
    int wm   = (w & 1) * 64;   // warp row offset
    int wn   = (w >> 1) * 32;  // warp col offset
    int lrow = lane & 15;
    int lcol = (lane >> 4) * 8;

    float acc[4][4][4];
#pragma unroll
    for (int i = 0; i < 4; i++)
#pragma unroll
        for (int j = 0; j < 4; j++)
#pragma unroll
            for (int k2 = 0; k2 < 4; k2++) acc[i][j][k2] = 0.f;

#pragma unroll
    for (int ks = 0; ks < 8; ks++) {
        int kb = ks * 16;
        unsigned a[4][4], b[2][4];
#pragma unroll
        for (int mt = 0; mt < 4; mt++) {
            const __half* pa = As + (wm + mt * 16 + lrow) * SMS + kb + lcol;
            ldsm4(a[mt], (uint32_t)__cvta_generic_to_shared(pa));
        }
#pragma unroll
        for (int np = 0; np < 2; np++) {
            const __half* pb = Bs + (kb + lrow) * SMS + wn + np * 16 + lcol;
            ldsm4t(b[np], (uint32_t)__cvta_generic_to_shared(pb));
        }
#pragma unroll
        for (int mt = 0; mt < 4; mt++)
#pragma unroll
            for (int nt = 0; nt < 4; nt++)
                mma16816(acc[mt][nt], a[mt], &b[nt >> 1][(nt & 1) * 2]);
    }

    // Epilogue: bias add + store.
    //   plane 12    -> d_out (fp32, self-loop base term)
    //   planes 0-3  -> g_K[t]          (fp16, stride 128)
    //   planes 4-7  -> g_QV[t] cols 0-127   (fp16, stride 256)
    //   planes 8-11 -> g_QV[t] cols 128-255 (fp16, stride 256)
    const float* bias = g_bias + plane * 128;
    int g  = lane >> 2;
    int tg = lane & 3;

    if (plane == 12) {
#pragma unroll
        for (int nt = 0; nt < 4; nt++) {
            int col = wn + nt * 8 + tg * 2;
            float b0 = bias[col], b1 = bias[col + 1];
#pragma unroll
            for (int mt = 0; mt < 4; mt++) {
                int r = rowBase + wm + mt * 16 + g;
                if (r < N)
                    *(float2*)(out + (size_t)r * 128 + col) =
                        make_float2(acc[mt][nt][0] + b0, acc[mt][nt][1] + b1);
                if (r + 8 < N)
                    *(float2*)(out + (size_t)(r + 8) * 128 + col) =
                        make_float2(acc[mt][nt][2] + b0, acc[mt][nt][3] + b1);
            }
        }
    } else {
        __half* hdst;
        int stride;
        if (plane < 4)      { hdst = g_K  + (size_t)plane * NPLANE_H;                 stride = 128; }
        else if (plane < 8) { hdst = g_QV + (size_t)(plane - 4) * 2 * NPLANE_H;       stride = 256; }
        else                { hdst = g_QV + (size_t)(plane - 8) * 2 * NPLANE_H + 128; stride = 256; }
#pragma unroll
        for (int nt = 0; nt < 4; nt++) {
            int col = wn + nt * 8 + tg * 2;
            float b0 = bias[col], b1 = bias[col + 1];
#pragma unroll
            for (int mt = 0; mt < 4; mt++) {
                int r = rowBase + wm + mt * 16 + g;
                if (r < N)
                    *(__half2*)(hdst + (size_t)r * stride + col) =
                        __floats2half2_rn(acc[mt][nt][0] + b0, acc[mt][nt][1] + b1);
                if (r + 8 < N)
                    *(__half2*)(hdst + (size_t)(r + 8) * stride + col) =
                        __floats2half2_rn(acc[mt][nt][2] + b0, acc[mt][nt][3] + b1);
            }
        }
    }
}

// ---------------------------------------------------------------------------
// Edge scatter for type t: out[dst] += sigmoid(K_t[dst]+Q_t[src]) * V'_t[src]
// (V' carries the 1/T factor). Ballot-compaction, 2 edges per iteration with
// all loads issued before the first red.global (its memory clobber would
// otherwise fence load hoisting). fp16 features: 768 B/edge read.
// ---------------------------------------------------------------------------
__device__ __forceinline__ float4 edge_msg(uint2 k, uint2 q, uint2 v)
{
    float2 ka = __half22float2(*(__half2*)&k.x), kb = __half22float2(*(__half2*)&k.y);
    float2 qa = __half22float2(*(__half2*)&q.x), qb = __half22float2(*(__half2*)&q.y);
    float2 va = __half22float2(*(__half2*)&v.x), vb = __half22float2(*(__half2*)&v.y);
    float4 r;
    r.x = va.x * __fdividef(1.f, 1.f + __expf(-(ka.x + qa.x)));
    r.y = va.y * __fdividef(1.f, 1.f + __expf(-(ka.y + qa.y)));
    r.z = vb.x * __fdividef(1.f, 1.f + __expf(-(kb.x + qb.x)));
    r.w = vb.y * __fdividef(1.f, 1.f + __expf(-(kb.y + qb.y)));
    return r;
}

__global__ void __launch_bounds__(256)
edge_kernel(const int* __restrict__ ei, const int* __restrict__ et,
            float* __restrict__ out, int E, int t)
{
    const uint2* K2  = (const uint2*)(g_K  + (size_t)t * NPLANE_H);      // 32 uint2 / node
    const uint2* QV2 = (const uint2*)(g_QV + (size_t)t * 2 * NPLANE_H);  // 64 uint2 / node

    int lane   = threadIdx.x & 31;
    int warp   = blockIdx.x * (blockDim.x >> 5) + (threadIdx.x >> 5);
    int nwarps = gridDim.x * (blockDim.x >> 5);

    for (int base = warp * 32; base < E; base += nwarps * 32) {
        int e  = base + lane;
        int ty = -1, s0 = 0, d0 = 0;
        if (e < E) { ty = et[e]; s0 = ei[e]; d0 = ei[E + e]; }
        unsigned m = __ballot_sync(0xffffffffu, ty == t);
        while (m) {
            int b0 = __ffs(m) - 1;  m &= (m - 1);
            int b1 = -1;
            if (m) { b1 = __ffs(m) - 1; m &= (m - 1); }

            int srcA = __shfl_sync(0xffffffffu, s0, b0);
            int dstA = __shfl_sync(0xffffffffu, d0, b0);
            int srcB = __shfl_sync(0xffffffffu, s0, (b1 >= 0) ? b1 : b0);
            int dstB = __shfl_sync(0xffffffffu, d0, (b1 >= 0) ? b1 : b0);

            // Issue all loads up front (max MLP before the atomics' memory clobber).
            uint2 kA = __ldg(&K2 [(size_t)dstA * 32 + lane]);
            uint2 qA = __ldg(&QV2[(size_t)srcA * 64 + lane]);
            uint2 vA = __ldg(&QV2[(size_t)srcA * 64 + 32 + lane]);
            uint2 kB, qB, vB;
            if (b1 >= 0) {
                kB = __ldg(&K2 [(size_t)dstB * 32 + lane]);
                qB = __ldg(&QV2[(size_t)srcB * 64 + lane]);
                vB = __ldg(&QV2[(size_t)srcB * 64 + 32 + lane]);
            }

            float4 rA = edge_msg(kA, qA, vA);
            float4 rB;
            if (b1 >= 0) rB = edge_msg(kB, qB, vB);

            float* pA = out + (size_t)dstA * 128 + lane * 4;
            asm volatile("red.global.add.v4.f32 [%0], {%1,%2,%3,%4};\n"
                         :: "l"(pA), "f"(rA.x), "f"(rA.y), "f"(rA.z), "f"(rA.w) : "memory");
            if (b1 >= 0) {
                float* pB = out + (size_t)dstB * 128 + lane * 4;
                asm volatile("red.global.add.v4.f32 [%0], {%1,%2,%3,%4};\n"
                             :: "l"(pB), "f"(rB.x), "f"(rB.y), "f"(rB.z), "f"(rB.w) : "memory");
            }
        }
    }
}

// ---------------------------------------------------------------------------
// Launch: pack -> GEMM (plane 12 initializes d_out) -> 4 per-type edge passes.
// ---------------------------------------------------------------------------
extern "C" void kernel_launch(void* const* d_in, const int* in_sizes, int n_in,
                              void* d_out, int out_size)
{
    const float* x  = (const float*)d_in[0];
    const int*   ei = (const int*)d_in[1];
    const int*   et = (const int*)d_in[2];
    const float* Wk = (const float*)d_in[3];
    const float* bk = (const float*)d_in[4];
    const float* Wq = (const float*)d_in[5];
    const float* bq = (const float*)d_in[6];
    const float* Wv = (const float*)d_in[7];
    const float* bv = (const float*)d_in[8];
    const float* Ws = (const float*)d_in[9];
    const float* bb = (const float*)d_in[10];
    float* out = (float*)d_out;

    int N = in_sizes[0] / 128;
    int E = in_sizes[2];

    const int smem_bytes = 2 * 128 * SMS * (int)sizeof(__half);  // 69632
    cudaFuncSetAttribute(gemm_kernel, cudaFuncAttributeMaxDynamicSharedMemorySize, smem_bytes);

    pack_weights_kernel<<<(13 * 16384 + 255) / 256, 256>>>(Wk, bk, Wq, bq, Wv, bv, Ws, bb);

    dim3 gg(13, (N + 127) / 128);
    gemm_kernel<<<gg, 256, smem_bytes>>>(x, out, N);

    for (int t = 0; t < 4; t++) {
        edge_kernel<<<2048, 256>>>(ei, et, out, E, t);
    }
}

// round 9
// speedup vs baseline: 1.8489x; 1.0078x over previous
#include <cuda_runtime.h>
#include <cuda_bf16.h>
#include <cuda_fp16.h>
#include <cstdint>

// Problem constants (shapes fixed by the dataset).
#define MAXN_NODES 50000
#define SMS 136                       // padded smem row stride in fp16 elems (128 + 8)
#define NPLANE_H ((size_t)MAXN_NODES * 128)

// Scratch (static device arrays; cudaMalloc is forbidden).
// g_K[t][node][128]  : K_t features, fp16
// g_QV[t][node][256] : Q_t (cols 0-127) and 0.25*V_t (cols 128-255) per node, fp16
__device__ __half g_K [(size_t)4 * MAXN_NODES * 128];
__device__ __half g_QV[(size_t)4 * MAXN_NODES * 256];
__device__ __half g_W [13 * 128 * 128];     // fp16 weight planes, [k][n]
__device__ float  g_bias[13 * 128];

// ---------------------------------------------------------------------------
// Pack weights into 13 [k=128][n=128] fp16 planes + fp32 bias vector.
// Planes: 0-3 Wk, 4-7 Wq, 8-11 0.25*Wv, 12 = 0.25*sum_t Ws[t].
// ---------------------------------------------------------------------------
__global__ void pack_weights_kernel(const float* __restrict__ Wk, const float* __restrict__ bk,
                                    const float* __restrict__ Wq, const float* __restrict__ bq,
                                    const float* __restrict__ Wv, const float* __restrict__ bv,
                                    const float* __restrict__ Ws, const float* __restrict__ bs)
{
    int idx = blockIdx.x * blockDim.x + threadIdx.x;
    if (idx < 13 * 16384) {
        int p   = idx >> 14;
        int off = idx & 16383;
        float v;
        if (p < 4)       v = Wk[p * 16384 + off];
        else if (p < 8)  v = Wq[(p - 4) * 16384 + off];
        else if (p < 12) v = 0.25f * Wv[(p - 8) * 16384 + off];
        else             v = 0.25f * (Ws[off] + Ws[16384 + off] + Ws[32768 + off] + Ws[49152 + off]);
        g_W[idx] = __float2half_rn(v);
    }
    if (idx < 13 * 128) {
        int p   = idx >> 7;
        int off = idx & 127;
        float v;
        if (p < 4)       v = bk[p * 128 + off];
        else if (p < 8)  v = bq[(p - 4) * 128 + off];
        else if (p < 12) v = 0.25f * bv[(p - 8) * 128 + off];
        else             v = 0.25f * (bs[off] + bs[128 + off] + bs[256 + off] + bs[384 + off]);
        g_bias[idx] = v;
    }
}

// ---------------------------------------------------------------------------
// mma/ldmatrix helpers
// ---------------------------------------------------------------------------
__device__ __forceinline__ void mma16816(float* c, const unsigned* a, const unsigned* b)
{
    asm volatile(
        "mma.sync.aligned.m16n8k16.row.col.f32.f16.f16.f32 "
        "{%0,%1,%2,%3}, {%4,%5,%6,%7}, {%8,%9}, {%0,%1,%2,%3};\n"
        : "+f"(c[0]), "+f"(c[1]), "+f"(c[2]), "+f"(c[3])
        : "r"(a[0]), "r"(a[1]), "r"(a[2]), "r"(a[3]), "r"(b[0]), "r"(b[1]));
}
__device__ __forceinline__ void ldsm4(unsigned* r, uint32_t addr)
{
    asm volatile("ldmatrix.sync.aligned.m8n8.x4.shared.b16 {%0,%1,%2,%3}, [%4];\n"
                 : "=r"(r[0]), "=r"(r[1]), "=r"(r[2]), "=r"(r[3]) : "r"(addr));
}
__device__ __forceinline__ void ldsm4t(unsigned* r, uint32_t addr)
{
    asm volatile("ldmatrix.sync.aligned.m8n8.x4.trans.shared.b16 {%0,%1,%2,%3}, [%4];\n"
                 : "=r"(r[0]), "=r"(r[1]), "=r"(r[2]), "=r"(r[3]) : "r"(addr));
}
__device__ __forceinline__ void cp_async16(uint32_t smem_dst, const void* gsrc)
{
    asm volatile("cp.async.cg.shared.global [%0], [%1], 16;\n" :: "r"(smem_dst), "l"(gsrc));
}

// ---------------------------------------------------------------------------
// Tensor-core GEMM: one CTA per 128-row tile computes ALL 13 output planes.
// X loaded ONCE per tile; W planes stream through a cp.async double buffer.
// 256 threads = 8 warps (2m x 4n), warp tile 64x32, K=128 in 8 steps of 16.
// ---------------------------------------------------------------------------
__global__ void __launch_bounds__(256, 2)
gemm_kernel(const float* __restrict__ X, float* __restrict__ out, int N)
{
    extern __shared__ __half sm[];
    __half* As = sm;                       // [128][SMS]
    __half* W0 = sm + 128 * SMS;           // W double buffer
    __half* W1 = sm + 2 * 128 * SMS;

    int rowBase = blockIdx.x * 128;
    int tid     = threadIdx.x;

    // Load x tile (fp32 -> fp16) once.
#pragma unroll
    for (int i = 0; i < 16; i++) {
        int chunk = tid + i * 256;
        int row = chunk >> 5;
        int c4  = (chunk & 31) * 4;
        int grow = rowBase + row;
        float4 v = make_float4(0.f, 0.f, 0.f, 0.f);
        if (grow < N) v = *(const float4*)(X + (size_t)grow * 128 + c4);
        __half2 h01 = __floats2half2_rn(v.x, v.y);
        __half2 h23 = __floats2half2_rn(v.z, v.w);
        uint2 packed = make_uint2(*(unsigned*)&h01, *(unsigned*)&h23);
        *(uint2*)(As + row * SMS + c4) = packed;
    }

    // Prefetch W plane 0 into buffer 0.
    {
        const __half* src = g_W;
#pragma unroll
        for (int i = 0; i < 8; i++) {
            int chunk = tid + i * 256;
            int row = chunk >> 4;
            int c8  = (chunk & 15) * 8;
            cp_async16((uint32_t)__cvta_generic_to_shared(W0 + row * SMS + c8), src + chunk * 8);
        }
        asm volatile("cp.async.commit_group;\n");
    }
    asm volatile("cp.async.wait_group 0;\n");
    __syncthreads();

    int w    = tid >> 5;
    int lane = tid & 31;
    int wm   = (w & 1) * 64;
    int wn   = (w >> 1) * 32;
    int lrow = lane & 15;
    int lcol = (lane >> 4) * 8;
    int g    = lane >> 2;
    int tg   = lane & 3;

    for (int p = 0; p < 13; p++) {
        __half* Bs = (p & 1) ? W1 : W0;
        __half* Bn = (p & 1) ? W0 : W1;

        // Prefetch next plane into the other buffer (last read at plane p-1,
        // protected by the __syncthreads at the end of iteration p-1).
        if (p < 12) {
            const __half* src = g_W + (p + 1) * 16384;
#pragma unroll
            for (int i = 0; i < 8; i++) {
                int chunk = tid + i * 256;
                int row = chunk >> 4;
                int c8  = (chunk & 15) * 8;
                cp_async16((uint32_t)__cvta_generic_to_shared(Bn + row * SMS + c8), src + chunk * 8);
            }
            asm volatile("cp.async.commit_group;\n");
        }

        float acc[4][4][4];
#pragma unroll
        for (int i = 0; i < 4; i++)
#pragma unroll
            for (int j = 0; j < 4; j++)
#pragma unroll
                for (int k2 = 0; k2 < 4; k2++) acc[i][j][k2] = 0.f;

#pragma unroll
        for (int ks = 0; ks < 8; ks++) {
            int kb = ks * 16;
            unsigned a[4][4], b[2][4];
#pragma unroll
            for (int mt = 0; mt < 4; mt++)
                ldsm4(a[mt], (uint32_t)__cvta_generic_to_shared(
                                 As + (wm + mt * 16 + lrow) * SMS + kb + lcol));
#pragma unroll
            for (int np = 0; np < 2; np++)
                ldsm4t(b[np], (uint32_t)__cvta_generic_to_shared(
                                  Bs + (kb + lrow) * SMS + wn + np * 16 + lcol));
#pragma unroll
            for (int mt = 0; mt < 4; mt++)
#pragma unroll
                for (int nt = 0; nt < 4; nt++)
                    mma16816(acc[mt][nt], a[mt], &b[nt >> 1][(nt & 1) * 2]);
        }

        // Epilogue for plane p (global writes only; overlaps the in-flight prefetch).
        const float* bias = g_bias + p * 128;
        if (p == 12) {
#pragma unroll
            for (int nt = 0; nt < 4; nt++) {
                int col = wn + nt * 8 + tg * 2;
                float b0 = bias[col], b1 = bias[col + 1];
#pragma unroll
                for (int mt = 0; mt < 4; mt++) {
                    int r = rowBase + wm + mt * 16 + g;
                    if (r < N)
                        *(float2*)(out + (size_t)r * 128 + col) =
                            make_float2(acc[mt][nt][0] + b0, acc[mt][nt][1] + b1);
                    if (r + 8 < N)
                        *(float2*)(out + (size_t)(r + 8) * 128 + col) =
                            make_float2(acc[mt][nt][2] + b0, acc[mt][nt][3] + b1);
                }
            }
        } else {
            __half* hdst;
            int stride;
            if (p < 4)      { hdst = g_K  + (size_t)p * NPLANE_H;                 stride = 128; }
            else if (p < 8) { hdst = g_QV + (size_t)(p - 4) * 2 * NPLANE_H;       stride = 256; }
            else            { hdst = g_QV + (size_t)(p - 8) * 2 * NPLANE_H + 128; stride = 256; }
#pragma unroll
            for (int nt = 0; nt < 4; nt++) {
                int col = wn + nt * 8 + tg * 2;
                float b0 = bias[col], b1 = bias[col + 1];
#pragma unroll
                for (int mt = 0; mt < 4; mt++) {
                    int r = rowBase + wm + mt * 16 + g;
                    if (r < N)
                        *(__half2*)(hdst + (size_t)r * stride + col) =
                            __floats2half2_rn(acc[mt][nt][0] + b0, acc[mt][nt][1] + b1);
                    if (r + 8 < N)
                        *(__half2*)(hdst + (size_t)(r + 8) * stride + col) =
                            __floats2half2_rn(acc[mt][nt][2] + b0, acc[mt][nt][3] + b1);
                }
            }
        }

        asm volatile("cp.async.wait_group 0;\n");
        __syncthreads();
    }
}

// ---------------------------------------------------------------------------
// Edge scatter for type t: out[dst] += sigmoid(K_t[dst]+Q_t[src]) * V'_t[src]
// (V' carries the 1/T factor). Ballot-compaction; 4 edges per iteration with
// all 12 loads issued before the first red.global (its memory clobber fences
// later load hoisting). fp16 features: 768 B/edge read.
// ---------------------------------------------------------------------------
__device__ __forceinline__ float4 edge_msg(uint2 k, uint2 q, uint2 v)
{
    float2 ka = __half22float2(*(__half2*)&k.x), kb = __half22float2(*(__half2*)&k.y);
    float2 qa = __half22float2(*(__half2*)&q.x), qb = __half22float2(*(__half2*)&q.y);
    float2 va = __half22float2(*(__half2*)&v.x), vb = __half22float2(*(__half2*)&v.y);
    float4 r;
    r.x = va.x * __fdividef(1.f, 1.f + __expf(-(ka.x + qa.x)));
    r.y = va.y * __fdividef(1.f, 1.f + __expf(-(ka.y + qa.y)));
    r.z = vb.x * __fdividef(1.f, 1.f + __expf(-(kb.x + qb.x)));
    r.w = vb.y * __fdividef(1.f, 1.f + __expf(-(kb.y + qb.y)));
    return r;
}

__global__ void __launch_bounds__(256)
edge_kernel(const int* __restrict__ ei, const int* __restrict__ et,
            float* __restrict__ out, int E, int t)
{
    const uint2* K2  = (const uint2*)(g_K  + (size_t)t * NPLANE_H);      // 32 uint2 / node
    const uint2* QV2 = (const uint2*)(g_QV + (size_t)t * 2 * NPLANE_H);  // 64 uint2 / node

    int lane   = threadIdx.x & 31;
    int warp   = blockIdx.x * (blockDim.x >> 5) + (threadIdx.x >> 5);
    int nwarps = gridDim.x * (blockDim.x >> 5);

    for (int base = warp * 32; base < E; base += nwarps * 32) {
        int e  = base + lane;
        int ty = -1, s0 = 0, d0 = 0;
        if (e < E) { ty = et[e]; s0 = ei[e]; d0 = ei[E + e]; }
        unsigned m = __ballot_sync(0xffffffffu, ty == t);
        while (m) {
            // Pop up to 4 matching edges (m is warp-uniform, so branches converge).
            int pc = __popc(m);
            int nb = pc < 4 ? pc : 4;
            int srcs[4], dsts[4];
#pragma unroll
            for (int u = 0; u < 4; u++) {
                int b = 0;
                if (u < nb) { b = __ffs(m) - 1; m &= (m - 1); }
                srcs[u] = __shfl_sync(0xffffffffu, s0, b);
                dsts[u] = __shfl_sync(0xffffffffu, d0, b);
            }

            // Issue every load before any atomic (max MLP).
            uint2 kk[4], qq[4], vv[4];
#pragma unroll
            for (int u = 0; u < 4; u++) {
                if (u < nb) {
                    kk[u] = __ldg(&K2 [(size_t)dsts[u] * 32 + lane]);
                    qq[u] = __ldg(&QV2[(size_t)srcs[u] * 64 + lane]);
                    vv[u] = __ldg(&QV2[(size_t)srcs[u] * 64 + 32 + lane]);
                }
            }

            float4 r[4];
#pragma unroll
            for (int u = 0; u < 4; u++)
                if (u < nb) r[u] = edge_msg(kk[u], qq[u], vv[u]);

#pragma unroll
            for (int u = 0; u < 4; u++) {
                if (u < nb) {
                    float* p = out + (size_t)dsts[u] * 128 + lane * 4;
                    asm volatile("red.global.add.v4.f32 [%0], {%1,%2,%3,%4};\n"
                                 :: "l"(p), "f"(r[u].x), "f"(r[u].y), "f"(r[u].z), "f"(r[u].w)
                                 : "memory");
                }
            }
        }
    }
}

// ---------------------------------------------------------------------------
// Launch: pack -> GEMM (plane 12 initializes d_out) -> 4 per-type edge passes.
// ---------------------------------------------------------------------------
extern "C" void kernel_launch(void* const* d_in, const int* in_sizes, int n_in,
                              void* d_out, int out_size)
{
    const float* x  = (const float*)d_in[0];
    const int*   ei = (const int*)d_in[1];
    const int*   et = (const int*)d_in[2];
    const float* Wk = (const float*)d_in[3];
    const float* bk = (const float*)d_in[4];
    const float* Wq = (const float*)d_in[5];
    const float* bq = (const float*)d_in[6];
    const float* Wv = (const float*)d_in[7];
    const float* bv = (const float*)d_in[8];
    const float* Ws = (const float*)d_in[9];
    const float* bb = (const float*)d_in[10];
    float* out = (float*)d_out;

    int N = in_sizes[0] / 128;
    int E = in_sizes[2];

    const int smem_bytes = 3 * 128 * SMS * (int)sizeof(__half);  // 104448
    cudaFuncSetAttribute(gemm_kernel, cudaFuncAttributeMaxDynamicSharedMemorySize, smem_bytes);

    pack_weights_kernel<<<(13 * 16384 + 255) / 256, 256>>>(Wk, bk, Wq, bq, Wv, bv, Ws, bb);

    gemm_kernel<<<(N + 127) / 128, 256, smem_bytes>>>(x, out, N);

    for (int t = 0; t < 4; t++) {
        edge_kernel<<<1184, 256>>>(ei, et, out, E, t);
    }
}